// round 1
// baseline (speedup 1.0000x reference)
#include <cuda_runtime.h>
#include <math.h>

#define EPS 1e-5f

// ---------------- scratch pool (floats) ----------------
// sized for b=4, D=H=W=32 (Bwin=2048, rows=131072)
#define OF_VOLA   0ull            // 4*32768*192 = 25165824
#define OF_VOLB   25165824ull     // 25165824
#define OF_QKV    50331648ull     // 131072*288 = 37748736
#define OF_XATT   88080384ull     // 131072*96  = 12582912
#define OF_AOUT   100663296ull    // 12582912
#define OF_VOLP   113246208ull    // 12582912
#define OF_YV     125829120ull    // 12582912
#define OF_S12    138412032ull    // 131072*12  = 1572864
#define OF_PCS    139984896ull    // 4096*192 = 786432
#define OF_PCQ    140771328ull    // 786432
#define OF_PPOOL  141557760ull    // 786432
#define OF_P12S   142344192ull    // 2048*12 = 24576
#define OF_P12Q   142368768ull
#define OF_PYS    142393344ull    // 2048*96 = 196608
#define OF_PYQ    142589952ull
#define OF_M1     142786560ull    // 768
#define OF_R1     142787328ull
#define OF_POOLED 142788096ull    // 768
#define OF_M2     142788864ull    // 48
#define OF_R2     142788912ull
#define OF_M3     142788960ull    // 384
#define OF_R3     142789344ull
#define OF_GATE   142789728ull    // 384

__device__ float g_pool[142800000];

__device__ __forceinline__ float geluf(float x) {
    return 0.5f * x * (1.0f + erff(x * 0.70710678118654752f));
}

// window-row -> true spatial index (b,Z,Y,X flattened), D=H=W=32, ws=4
__device__ __forceinline__ int spatial_of_row(int row) {
    int win = row >> 6, n = row & 63;
    int b = win >> 9, d = (win >> 6) & 7, h = (win >> 3) & 7, w = win & 7;
    int wd = n >> 4, wh = (n >> 2) & 3, ww = n & 3;
    int Z = d * 4 + wd, Y = h * 4 + wh, X = w * 4 + ww;
    return ((b * 32 + Z) * 32 + Y) * 32 + X;
}

// ============================================================
// K1: fused embed GEMM: X(rows,192) @ [w_pattn(192,96) | w_pcnn(192,192)]
//     + bias + LN(96) -> x_atten0 ; + LN(192) -> volA (spatial, channel-last)
// grid rows/32, block 288
// ============================================================
__global__ __launch_bounds__(288) void k_embed(
    const float* __restrict__ x,
    const float* __restrict__ w1, const float* __restrict__ b1,
    const float* __restrict__ ga, const float* __restrict__ ba,
    const float* __restrict__ w2, const float* __restrict__ b2,
    const float* __restrict__ gc, const float* __restrict__ bc)
{
    __shared__ union {
        struct { float sAT[16][32]; float sW[16][288]; } s;
        float sOut[32][288];
    } sm;
    const int tid = threadIdx.x;
    const int row0 = blockIdx.x * 32;
    const int rg = tid / 36, cg = tid % 36;
    float acc[4][8];
#pragma unroll
    for (int i = 0; i < 4; i++)
#pragma unroll
        for (int j = 0; j < 8; j++) acc[i][j] = 0.f;

    for (int kb = 0; kb < 192; kb += 16) {
        if (tid < 128) {
            int r = tid >> 2, q = tid & 3;
            float4 v = *(const float4*)(x + (size_t)(row0 + r) * 192 + kb + q * 4);
            sm.s.sAT[q * 4 + 0][r] = v.x; sm.s.sAT[q * 4 + 1][r] = v.y;
            sm.s.sAT[q * 4 + 2][r] = v.z; sm.s.sAT[q * 4 + 3][r] = v.w;
        }
#pragma unroll
        for (int i = 0; i < 4; i++) {
            int lin = tid + i * 288; int k = lin / 72; int c = (lin % 72) * 4;
            float4 v;
            if (c < 96) v = *(const float4*)(w1 + (size_t)(kb + k) * 96 + c);
            else        v = *(const float4*)(w2 + (size_t)(kb + k) * 192 + (c - 96));
            *(float4*)&sm.s.sW[k][c] = v;
        }
        __syncthreads();
#pragma unroll
        for (int k = 0; k < 16; k++) {
            float4 a4 = *(float4*)&sm.s.sAT[k][rg * 4];
            float4 wA = *(float4*)&sm.s.sW[k][cg * 8];
            float4 wB = *(float4*)&sm.s.sW[k][cg * 8 + 4];
            float av[4] = {a4.x, a4.y, a4.z, a4.w};
            float wv[8] = {wA.x, wA.y, wA.z, wA.w, wB.x, wB.y, wB.z, wB.w};
#pragma unroll
            for (int i = 0; i < 4; i++)
#pragma unroll
                for (int j = 0; j < 8; j++) acc[i][j] += av[i] * wv[j];
        }
        __syncthreads();
    }
    // stage to smem with bias
#pragma unroll
    for (int i = 0; i < 4; i++) {
        int r = rg * 4 + i;
#pragma unroll
        for (int j = 0; j < 8; j++) {
            int c = cg * 8 + j;
            float bias = (c < 96) ? b1[c] : b2[c - 96];
            sm.sOut[r][c] = acc[i][j] + bias;
        }
    }
    __syncthreads();

    int warp = tid >> 5, lane = tid & 31; // 9 warps
    for (int r = warp; r < 32; r += 9) {
        int row = row0 + r;
        // atten LN over 96
        float s = 0.f, q = 0.f;
#pragma unroll
        for (int i = 0; i < 3; i++) { float v = sm.sOut[r][lane + 32 * i]; s += v; q += v * v; }
#pragma unroll
        for (int o = 16; o; o >>= 1) { s += __shfl_xor_sync(~0u, s, o); q += __shfl_xor_sync(~0u, q, o); }
        float m = s * (1.f / 96.f);
        float rs = rsqrtf(fmaxf(q * (1.f / 96.f) - m * m, 0.f) + EPS);
        float* xao = g_pool + OF_XATT + (size_t)row * 96;
#pragma unroll
        for (int i = 0; i < 3; i++) {
            int c = lane + 32 * i;
            xao[c] = (sm.sOut[r][c] - m) * rs * ga[c] + ba[c];
        }
        // cnn LN over 192
        s = 0.f; q = 0.f;
#pragma unroll
        for (int i = 0; i < 6; i++) { float v = sm.sOut[r][96 + lane + 32 * i]; s += v; q += v * v; }
#pragma unroll
        for (int o = 16; o; o >>= 1) { s += __shfl_xor_sync(~0u, s, o); q += __shfl_xor_sync(~0u, q, o); }
        m = s * (1.f / 192.f);
        rs = rsqrtf(fmaxf(q * (1.f / 192.f) - m * m, 0.f) + EPS);
        float* va = g_pool + OF_VOLA + (size_t)spatial_of_row(row) * 192;
#pragma unroll
        for (int i = 0; i < 6; i++) {
            int c = lane + 32 * i;
            va[c] = (sm.sOut[r][96 + c] - m) * rs * gc[c] + bc[c];
        }
    }
}

// ============================================================
// K2: depthwise conv 3x3x3 (pad 1) + bias, channel-last vol
// grid nb*32*32 (b,z,y), block 192 (=channel). Emits per-(b,c) partials.
// ============================================================
__global__ __launch_bounds__(192) void k_dwconv(
    const float* __restrict__ dww, const float* __restrict__ dwb)
{
    const float* vin = g_pool + OF_VOLA;
    float* vout = g_pool + OF_VOLB;
    int c = threadIdx.x;
    int blk = blockIdx.x;
    int b = blk >> 10, z = (blk >> 5) & 31, y = blk & 31;

    float w[27];
#pragma unroll
    for (int i = 0; i < 27; i++) w[i] = dww[c * 27 + i];
    float bias = dwb[c];

    const float* lbase[9];
    bool lv[9];
#pragma unroll
    for (int dz = 0; dz < 3; dz++)
#pragma unroll
        for (int dy = 0; dy < 3; dy++) {
            int l = dz * 3 + dy;
            int zz = z + dz - 1, yy = y + dy - 1;
            lv[l] = (zz >= 0 && zz < 32 && yy >= 0 && yy < 32);
            lbase[l] = vin + ((size_t)((b * 32 + zz) * 32 + yy) * 32) * 192 + c;
        }
    float p0[9], p1[9];
#pragma unroll
    for (int l = 0; l < 9; l++) { p0[l] = 0.f; p1[l] = lv[l] ? lbase[l][0] : 0.f; }

    float ssum = 0.f, ssq = 0.f;
    float* orow = vout + ((size_t)blk * 32) * 192 + c;
    for (int xx = 0; xx < 32; xx++) {
        float p2[9];
#pragma unroll
        for (int l = 0; l < 9; l++)
            p2[l] = (lv[l] && xx + 1 < 32) ? lbase[l][(size_t)(xx + 1) * 192] : 0.f;
        float a = bias;
#pragma unroll
        for (int l = 0; l < 9; l++)
            a += w[l * 3 + 0] * p0[l] + w[l * 3 + 1] * p1[l] + w[l * 3 + 2] * p2[l];
        orow[(size_t)xx * 192] = a;
        ssum += a; ssq += a * a;
#pragma unroll
        for (int l = 0; l < 9; l++) { p0[l] = p1[l]; p1[l] = p2[l]; }
    }
    g_pool[OF_PCS + (size_t)blk * 192 + c] = ssum;
    g_pool[OF_PCQ + (size_t)blk * 192 + c] = ssq;
}

// ============================================================
// generic deterministic reductions
// ============================================================
__global__ __launch_bounds__(128) void k_redstats(
    unsigned long long ofs, unsigned long long ofq, int nchunk, int C, float invN,
    unsigned long long ofm, unsigned long long ofr)
{
    __shared__ float ss[128], qq[128];
    int g = blockIdx.x; int b = g / C, c = g % C;
    float s = 0.f, q = 0.f;
    for (int i = threadIdx.x; i < nchunk; i += 128) {
        size_t o = ((size_t)b * nchunk + i) * C + c;
        s += g_pool[ofs + o]; q += g_pool[ofq + o];
    }
    ss[threadIdx.x] = s; qq[threadIdx.x] = q; __syncthreads();
    for (int o = 64; o; o >>= 1) {
        if (threadIdx.x < o) { ss[threadIdx.x] += ss[threadIdx.x + o]; qq[threadIdx.x] += qq[threadIdx.x + o]; }
        __syncthreads();
    }
    if (threadIdx.x == 0) {
        float m = ss[0] * invN;
        g_pool[ofm + g] = m;
        g_pool[ofr + g] = rsqrtf(fmaxf(qq[0] * invN - m * m, 0.f) + EPS);
    }
}

__global__ __launch_bounds__(128) void k_redmean(
    unsigned long long ofs, int nchunk, int C, float invN, unsigned long long ofm)
{
    __shared__ float ss[128];
    int g = blockIdx.x; int b = g / C, c = g % C;
    float s = 0.f;
    for (int i = threadIdx.x; i < nchunk; i += 128)
        s += g_pool[ofs + ((size_t)b * nchunk + i) * C + c];
    ss[threadIdx.x] = s; __syncthreads();
    for (int o = 64; o; o >>= 1) {
        if (threadIdx.x < o) ss[threadIdx.x] += ss[threadIdx.x + o];
        __syncthreads();
    }
    if (threadIdx.x == 0) g_pool[ofm + g] = ss[0] * invN;
}

// ============================================================
// K4: instance norm + gelu in place on volB, pooled partials
// grid nb*1024, block 192
// ============================================================
__global__ __launch_bounds__(192) void k_normgelu()
{
    int c = threadIdx.x;
    int blk = blockIdx.x; int b = blk >> 10;
    float m = g_pool[OF_M1 + b * 192 + c], rs = g_pool[OF_R1 + b * 192 + c];
    float* v = g_pool + OF_VOLB + ((size_t)blk * 32) * 192 + c;
    float s = 0.f;
    for (int xx = 0; xx < 32; xx++) {
        float t = (v[(size_t)xx * 192] - m) * rs;
        t = geluf(t);
        v[(size_t)xx * 192] = t;
        s += t;
    }
    g_pool[OF_PPOOL + (size_t)blk * 192 + c] = s;
}

// ============================================================
// K5: ci MLP (192->24 gelu ->96) + sigmoid gate. single block, 96 threads
// ============================================================
__global__ __launch_bounds__(96) void k_ci(
    const float* __restrict__ w1, const float* __restrict__ b1,
    const float* __restrict__ w2, const float* __restrict__ b2, int nb)
{
    __shared__ float t24[24];
    int tid = threadIdx.x;
    for (int b = 0; b < nb; b++) {
        if (tid < 24) {
            float s = b1[tid];
            for (int c = 0; c < 192; c++) s += g_pool[OF_POOLED + b * 192 + c] * w1[c * 24 + tid];
            t24[tid] = geluf(s);
        }
        __syncthreads();
        {
            float s = b2[tid];
#pragma unroll
            for (int j = 0; j < 24; j++) s += t24[j] * w2[j * 96 + tid];
            g_pool[OF_GATE + b * 96 + tid] = 1.f / (1.f + expf(-s));
        }
        __syncthreads();
    }
}

// ============================================================
// K6: pj conv1x1: volB(spatial gather, 192) @ pj_w(192,96) -> volP(window rows)
// grid rows/32, block 192
// ============================================================
__global__ __launch_bounds__(192) void k_pj(
    const float* __restrict__ pw, const float* __restrict__ pb)
{
    __shared__ float sAT[16][32];
    __shared__ float sW[16][96];
    int tid = threadIdx.x;
    int row0 = blockIdx.x * 32;
    int rg = tid / 24, cg = tid % 24;
    float acc[4][4];
#pragma unroll
    for (int i = 0; i < 4; i++)
#pragma unroll
        for (int j = 0; j < 4; j++) acc[i][j] = 0.f;
    const float* vb = g_pool + OF_VOLB;
    for (int kb = 0; kb < 192; kb += 16) {
        if (tid < 128) {
            int r = tid >> 2, q = tid & 3;
            float4 v = *(const float4*)(vb + (size_t)spatial_of_row(row0 + r) * 192 + kb + q * 4);
            sAT[q * 4 + 0][r] = v.x; sAT[q * 4 + 1][r] = v.y;
            sAT[q * 4 + 2][r] = v.z; sAT[q * 4 + 3][r] = v.w;
        }
#pragma unroll
        for (int i = 0; i < 2; i++) {
            int lin = tid + i * 192; int k = lin / 24; int c = (lin % 24) * 4;
            *(float4*)&sW[k][c] = *(const float4*)(pw + (size_t)(kb + k) * 96 + c);
        }
        __syncthreads();
#pragma unroll
        for (int k = 0; k < 16; k++) {
            float4 a4 = *(float4*)&sAT[k][rg * 4];
            float4 w4 = *(float4*)&sW[k][cg * 4];
            float av[4] = {a4.x, a4.y, a4.z, a4.w};
            float wv[4] = {w4.x, w4.y, w4.z, w4.w};
#pragma unroll
            for (int i = 0; i < 4; i++)
#pragma unroll
                for (int j = 0; j < 4; j++) acc[i][j] += av[i] * wv[j];
        }
        __syncthreads();
    }
    float* vp = g_pool + OF_VOLP;
#pragma unroll
    for (int i = 0; i < 4; i++) {
        int row = row0 + rg * 4 + i;
#pragma unroll
        for (int j = 0; j < 4; j++) {
            int c = cg * 4 + j;
            vp[(size_t)row * 96 + c] = acc[i][j] + pb[c];
        }
    }
}

// ============================================================
// K7a: qkv GEMM: x_atten0(rows,96) @ qkv_w(96,288) + b
// grid rows/32, block 288
// ============================================================
__global__ __launch_bounds__(288) void k_qkv(
    const float* __restrict__ w, const float* __restrict__ bias)
{
    __shared__ float sAT[16][32];
    __shared__ float sW[16][288];
    int tid = threadIdx.x;
    int row0 = blockIdx.x * 32;
    int rg = tid / 36, cg = tid % 36;
    float acc[4][8];
#pragma unroll
    for (int i = 0; i < 4; i++)
#pragma unroll
        for (int j = 0; j < 8; j++) acc[i][j] = 0.f;
    const float* A = g_pool + OF_XATT;
    for (int kb = 0; kb < 96; kb += 16) {
        if (tid < 128) {
            int r = tid >> 2, q = tid & 3;
            float4 v = *(const float4*)(A + (size_t)(row0 + r) * 96 + kb + q * 4);
            sAT[q * 4 + 0][r] = v.x; sAT[q * 4 + 1][r] = v.y;
            sAT[q * 4 + 2][r] = v.z; sAT[q * 4 + 3][r] = v.w;
        }
#pragma unroll
        for (int i = 0; i < 4; i++) {
            int lin = tid + i * 288; int k = lin / 72; int c = (lin % 72) * 4;
            *(float4*)&sW[k][c] = *(const float4*)(w + (size_t)(kb + k) * 288 + c);
        }
        __syncthreads();
#pragma unroll
        for (int k = 0; k < 16; k++) {
            float4 a4 = *(float4*)&sAT[k][rg * 4];
            float4 wA = *(float4*)&sW[k][cg * 8];
            float4 wB = *(float4*)&sW[k][cg * 8 + 4];
            float av[4] = {a4.x, a4.y, a4.z, a4.w};
            float wv[8] = {wA.x, wA.y, wA.z, wA.w, wB.x, wB.y, wB.z, wB.w};
#pragma unroll
            for (int i = 0; i < 4; i++)
#pragma unroll
                for (int j = 0; j < 8; j++) acc[i][j] += av[i] * wv[j];
        }
        __syncthreads();
    }
    float* Q = g_pool + OF_QKV;
#pragma unroll
    for (int i = 0; i < 4; i++) {
        int row = row0 + rg * 4 + i;
#pragma unroll
        for (int j = 0; j < 8; j++) {
            int c = cg * 8 + j;
            Q[(size_t)row * 288 + c] = acc[i][j] + bias[c];
        }
    }
}

// ============================================================
// K7b: attention per window, 6 heads, gated V, rel-pos bias inline
// grid Bwin, block 256
// ============================================================
__global__ __launch_bounds__(256) void k_attn(const float* __restrict__ rpb)
{
    __shared__ float qS[64][17], kS[64][17], vS[64][17], pS[64][65];
    int tid = threadIdx.x;
    int win = blockIdx.x; int b = win >> 9;
    const float* qkv = g_pool + OF_QKV + (size_t)win * 64 * 288;
    float* out = g_pool + OF_AOUT + (size_t)win * 64 * 96;
    int warp = tid >> 5, lane = tid & 31;

    for (int hh = 0; hh < 6; hh++) {
        __syncthreads();
#pragma unroll
        for (int i = 0; i < 4; i++) {
            int idx = tid + i * 256; int n = idx >> 4, d = idx & 15;
            size_t base = (size_t)n * 288 + hh * 16 + d;
            qS[n][d] = qkv[base] * 0.25f;
            kS[n][d] = qkv[base + 96];
            vS[n][d] = qkv[base + 192] * g_pool[OF_GATE + b * 96 + hh * 16 + d];
        }
        __syncthreads();
        for (int rr = 0; rr < 8; rr++) {
            int n = warp * 8 + rr;
            int nd = n >> 4, nh = (n >> 2) & 3, nw = n & 3;
            int m0 = lane, m1 = lane + 32;
            float s0 = 0.f, s1 = 0.f;
#pragma unroll
            for (int d = 0; d < 16; d++) {
                float qv = qS[n][d];
                s0 += qv * kS[m0][d];
                s1 += qv * kS[m1][d];
            }
            {
                int md = m0 >> 4, mh = (m0 >> 2) & 3, mw = m0 & 3;
                s0 += rpb[((nd - md + 3) * 49 + (nh - mh + 3) * 7 + (nw - mw + 3)) * 6 + hh];
                md = m1 >> 4; mh = (m1 >> 2) & 3; mw = m1 & 3;
                s1 += rpb[((nd - md + 3) * 49 + (nh - mh + 3) * 7 + (nw - mw + 3)) * 6 + hh];
            }
            float mx = fmaxf(s0, s1);
#pragma unroll
            for (int o = 16; o; o >>= 1) mx = fmaxf(mx, __shfl_xor_sync(~0u, mx, o));
            float e0 = expf(s0 - mx), e1 = expf(s1 - mx);
            float sum = e0 + e1;
#pragma unroll
            for (int o = 16; o; o >>= 1) sum += __shfl_xor_sync(~0u, sum, o);
            float inv = 1.f / sum;
            pS[n][m0] = e0 * inv;
            pS[n][m1] = e1 * inv;
        }
        __syncthreads();
        {
            int n = tid >> 2, dg = tid & 3;
            float a0 = 0.f, a1 = 0.f, a2 = 0.f, a3 = 0.f;
#pragma unroll
            for (int m = 0; m < 64; m++) {
                float pm = pS[n][m];
                a0 += pm * vS[m][dg * 4 + 0];
                a1 += pm * vS[m][dg * 4 + 1];
                a2 += pm * vS[m][dg * 4 + 2];
                a3 += pm * vS[m][dg * 4 + 3];
            }
            size_t ob = (size_t)n * 96 + hh * 16 + dg * 4;
            out[ob + 0] = a0; out[ob + 1] = a1; out[ob + 2] = a2; out[ob + 3] = a3;
        }
    }
}

// ============================================================
// K8a: si stage 1: attn_out(rows,96) @ si_w1(96,12) + b1 -> s12, partials
// grid rows/64, block 256
// ============================================================
__global__ __launch_bounds__(256) void k_si1(
    const float* __restrict__ w1, const float* __restrict__ b1)
{
    __shared__ float aS[64][97];
    __shared__ float wS[96 * 12];
    __shared__ float sb[64][12];
    int tid = threadIdx.x;
    int blk = blockIdx.x; int row0 = blk * 64;
    const float* A = g_pool + OF_AOUT;
    for (int i = tid; i < 96 * 12; i += 256) wS[i] = w1[i];
    for (int i = tid; i < 64 * 96; i += 256) {
        int r = i / 96, c = i % 96;
        aS[r][c] = A[(size_t)(row0 + r) * 96 + c];
    }
    __syncthreads();
    if (tid < 64) {
        float s[12];
#pragma unroll
        for (int j = 0; j < 12; j++) s[j] = b1[j];
        for (int c = 0; c < 96; c++) {
            float a = aS[tid][c];
#pragma unroll
            for (int j = 0; j < 12; j++) s[j] += a * wS[c * 12 + j];
        }
        float* o = g_pool + OF_S12 + (size_t)(row0 + tid) * 12;
#pragma unroll
        for (int j = 0; j < 12; j++) { o[j] = s[j]; sb[tid][j] = s[j]; }
    }
    __syncthreads();
    if (tid < 12) {
        float S = 0.f, Q = 0.f;
        for (int r = 0; r < 64; r++) { float v = sb[r][tid]; S += v; Q += v * v; }
        g_pool[OF_P12S + (size_t)blk * 12 + tid] = S;
        g_pool[OF_P12Q + (size_t)blk * 12 + tid] = Q;
    }
}

// ============================================================
// K8c: gate = sigmoid(gelu(inorm(s12)) @ si_w2 + b2); y = gate*volP; partials
// grid rows/64, block 96
// ============================================================
__global__ __launch_bounds__(96) void k_gatemul(
    const float* __restrict__ w2, const float* __restrict__ b2)
{
    __shared__ float gb[64];
    int tid = threadIdx.x;
    int blk = blockIdx.x; int row0 = blk * 64; int b = row0 >> 15;
    if (tid < 64) {
        const float* s = g_pool + OF_S12 + (size_t)(row0 + tid) * 12;
        float a = b2[0];
#pragma unroll
        for (int j = 0; j < 12; j++) {
            float v = (s[j] - g_pool[OF_M2 + b * 12 + j]) * g_pool[OF_R2 + b * 12 + j];
            a += geluf(v) * w2[j];
        }
        gb[tid] = 1.f / (1.f + expf(-a));
    }
    __syncthreads();
    const float* vp = g_pool + OF_VOLP + (size_t)row0 * 96 + tid;
    float* yv = g_pool + OF_YV + (size_t)row0 * 96 + tid;
    float ss = 0.f, sq = 0.f;
    for (int r = 0; r < 64; r++) {
        float y = gb[r] * vp[(size_t)r * 96];
        yv[(size_t)r * 96] = y;
        ss += y; sq += y * y;
    }
    g_pool[OF_PYS + (size_t)blk * 96 + tid] = ss;
    g_pool[OF_PYQ + (size_t)blk * 96 + tid] = sq;
}

// ============================================================
// K9: final: [LN(attn_out) | inorm(yv)] (rows,192) @ w_proj(192,192) + b -> out
// grid rows/32, block 192
// ============================================================
__global__ __launch_bounds__(192) void k_final(
    const float* __restrict__ wp, const float* __restrict__ bp,
    const float* __restrict__ ga, const float* __restrict__ ba,
    float* __restrict__ out)
{
    __shared__ float sAT[192][36];
    __shared__ float sW[16][192];
    int tid = threadIdx.x;
    int row0 = blockIdx.x * 32; int b = row0 >> 15;
    const float* A = g_pool + OF_AOUT;
    for (int i = 0; i < 16; i++) {
        int idx = tid + i * 192; int r = idx / 96, c = idx % 96;
        sAT[c][r] = A[(size_t)(row0 + r) * 96 + c];
    }
    __syncthreads();
    int warp = tid >> 5, lane = tid & 31; // 6 warps
    for (int r = warp; r < 32; r += 6) {
        float s = 0.f, q = 0.f;
#pragma unroll
        for (int i = 0; i < 3; i++) { float v = sAT[lane + 32 * i][r]; s += v; q += v * v; }
#pragma unroll
        for (int o = 16; o; o >>= 1) { s += __shfl_xor_sync(~0u, s, o); q += __shfl_xor_sync(~0u, q, o); }
        float m = s * (1.f / 96.f);
        float rs = rsqrtf(fmaxf(q * (1.f / 96.f) - m * m, 0.f) + EPS);
#pragma unroll
        for (int i = 0; i < 3; i++) {
            int c = lane + 32 * i;
            sAT[c][r] = (sAT[c][r] - m) * rs * ga[c] + ba[c];
        }
    }
    const float* Y = g_pool + OF_YV;
    for (int i = 0; i < 16; i++) {
        int idx = tid + i * 192; int r = idx / 96, c = idx % 96;
        sAT[96 + c][r] = (Y[(size_t)(row0 + r) * 96 + c] - g_pool[OF_M3 + b * 96 + c]) * g_pool[OF_R3 + b * 96 + c];
    }
    __syncthreads();

    int rg = tid / 24, cg = tid % 24;
    float acc[4][8];
#pragma unroll
    for (int i = 0; i < 4; i++)
#pragma unroll
        for (int j = 0; j < 8; j++) acc[i][j] = 0.f;
    for (int kb = 0; kb < 192; kb += 16) {
#pragma unroll
        for (int i = 0; i < 4; i++) {
            int lin = tid + i * 192; int k = lin / 48; int c = (lin % 48) * 4;
            *(float4*)&sW[k][c] = *(const float4*)(wp + (size_t)(kb + k) * 192 + c);
        }
        __syncthreads();
#pragma unroll
        for (int k = 0; k < 16; k++) {
            float4 a4 = *(float4*)&sAT[kb + k][rg * 4];
            float4 wA = *(float4*)&sW[k][cg * 8];
            float4 wB = *(float4*)&sW[k][cg * 8 + 4];
            float av[4] = {a4.x, a4.y, a4.z, a4.w};
            float wv[8] = {wA.x, wA.y, wA.z, wA.w, wB.x, wB.y, wB.z, wB.w};
#pragma unroll
            for (int i = 0; i < 4; i++)
#pragma unroll
                for (int j = 0; j < 8; j++) acc[i][j] += av[i] * wv[j];
        }
        __syncthreads();
    }
#pragma unroll
    for (int i = 0; i < 4; i++) {
        int row = row0 + rg * 4 + i;
#pragma unroll
        for (int j = 0; j < 8; j++) {
            int c = cg * 8 + j;
            out[(size_t)row * 192 + c] = acc[i][j] + bp[c];
        }
    }
}

// ============================================================
// host launcher
// ============================================================
extern "C" void kernel_launch(void* const* d_in, const int* in_sizes, int n_in,
                              void* d_out, int out_size)
{
    const float* x       = (const float*)d_in[0];
    const float* w_pattn = (const float*)d_in[1];
    const float* b_pattn = (const float*)d_in[2];
    const float* g_aln   = (const float*)d_in[3];
    const float* b_aln   = (const float*)d_in[4];
    const float* w_pcnn  = (const float*)d_in[5];
    const float* b_pcnn  = (const float*)d_in[6];
    const float* g_cln   = (const float*)d_in[7];
    const float* b_cln   = (const float*)d_in[8];
    const float* dw_w    = (const float*)d_in[9];
    const float* dw_b    = (const float*)d_in[10];
    const float* ci_w1   = (const float*)d_in[11];
    const float* ci_b1   = (const float*)d_in[12];
    const float* ci_w2   = (const float*)d_in[13];
    const float* ci_b2   = (const float*)d_in[14];
    const float* pj_w    = (const float*)d_in[15];
    const float* pj_b    = (const float*)d_in[16];
    const float* qkv_w   = (const float*)d_in[17];
    const float* qkv_b   = (const float*)d_in[18];
    const float* si_w1   = (const float*)d_in[19];
    const float* si_b1   = (const float*)d_in[20];
    const float* si_w2   = (const float*)d_in[21];
    const float* si_b2   = (const float*)d_in[22];
    const float* g_anorm = (const float*)d_in[23];
    const float* b_anorm = (const float*)d_in[24];
    const float* w_proj  = (const float*)d_in[25];
    const float* b_proj  = (const float*)d_in[26];
    const float* rpb     = (const float*)d_in[27];

    const int Bwin = in_sizes[0] / (64 * 192);   // 2048
    const int rows = Bwin * 64;                  // 131072
    const int nb   = Bwin / 512;                 // 4 (D=H=W=32, ws=4)

    k_embed<<<rows / 32, 288>>>(x, w_pattn, b_pattn, g_aln, b_aln,
                                w_pcnn, b_pcnn, g_cln, b_cln);
    k_dwconv<<<nb * 1024, 192>>>(dw_w, dw_b);
    k_redstats<<<nb * 192, 128>>>(OF_PCS, OF_PCQ, 1024, 192, 1.f / 32768.f, OF_M1, OF_R1);
    k_normgelu<<<nb * 1024, 192>>>();
    k_redmean<<<nb * 192, 128>>>(OF_PPOOL, 1024, 192, 1.f / 32768.f, OF_POOLED);
    k_ci<<<1, 96>>>(ci_w1, ci_b1, ci_w2, ci_b2, nb);
    k_pj<<<rows / 32, 192>>>(pj_w, pj_b);
    k_qkv<<<rows / 32, 288>>>(qkv_w, qkv_b);
    k_attn<<<Bwin, 256>>>(rpb);
    k_si1<<<rows / 64, 256>>>(si_w1, si_b1);
    k_redstats<<<nb * 12, 128>>>(OF_P12S, OF_P12Q, 512, 12, 1.f / 32768.f, OF_M2, OF_R2);
    k_gatemul<<<rows / 64, 96>>>(si_w2, si_b2);
    k_redstats<<<nb * 96, 128>>>(OF_PYS, OF_PYQ, 512, 96, 1.f / 32768.f, OF_M3, OF_R3);
    k_final<<<rows / 32, 192>>>(w_proj, b_proj, g_anorm, b_anorm, (float*)d_out);
}